// round 1
// baseline (speedup 1.0000x reference)
#include <cuda_runtime.h>
#include <math.h>

#define NN 4096

// ---------------- scratch (device globals; no runtime allocation) ----------------
__device__ float g_P[(size_t)NN * NN];        // 64 MB attention weights (unnormalized)
__device__ float g_hA[NN * 512];              // conv1 h
__device__ float g_out1[NN * 512];            // conv1 output (input to heads)
__device__ float g_cat[NN * 1536];            // concatenated head outputs / GN in-place
__device__ float g_hB[NN * 256];              // per-head / conv2 h
__device__ float g_l1[NN * 64];
__device__ float g_l2[NN * 64];
__device__ float g_s[NN];
__device__ float g_t[NN];
__device__ float g_invZ[NN];
__device__ unsigned g_mask[NN * 128];         // bit-packed adjacency
__device__ float g_part[2 * 2048];
__device__ float g_stats[2];

// ---------------- bitmask pack ----------------
__global__ void pack_mask_k(const int* __restrict__ adj, unsigned* __restrict__ mask) {
    int i = blockIdx.x;
    int w = threadIdx.x;               // 0..127
    const int* row = adj + (size_t)i * NN + w * 32;
    unsigned bits = 0;
#pragma unroll
    for (int b = 0; b < 32; b++) bits |= (row[b] > 0 ? 1u : 0u) << b;
    mask[i * 128 + w] = bits;
}

// ---------------- generic tiled SGEMM: C = A[MxK] * B[KxN], fused epilogue ----------------
// BM=BN=64, BK=16, 256 threads, 4x4 microtile. All dims multiples of tile sizes here.
__global__ __launch_bounds__(256) void sgemm64_k(
    const float* __restrict__ A, const float* __restrict__ B, float* __restrict__ C,
    int K, int lda, int ldb, int ldc,
    const float* __restrict__ bias, const float* __restrict__ rowScale, int act) {
    __shared__ float As[16][64];
    __shared__ float Bs[16][64];
    const int tid = threadIdx.x;
    const int tx = tid & 15, ty = tid >> 4;
    const int row0 = blockIdx.y * 64, col0 = blockIdx.x * 64;
    const int arow = tid >> 2;             // 0..63
    const int akq = (tid & 3) << 2;        // 0,4,8,12
    const int bk = tid >> 4;               // 0..15
    const int bc = (tid & 15) << 2;        // 0..60

    float acc[4][4];
#pragma unroll
    for (int i = 0; i < 4; i++)
#pragma unroll
        for (int j = 0; j < 4; j++) acc[i][j] = 0.f;

    const float* Aptr = A + (size_t)(row0 + arow) * lda + akq;
    const float* Bptr = B + (size_t)bk * ldb + col0 + bc;

    for (int k0 = 0; k0 < K; k0 += 16) {
        float4 av = *(const float4*)(Aptr + k0);
        As[akq + 0][arow] = av.x;
        As[akq + 1][arow] = av.y;
        As[akq + 2][arow] = av.z;
        As[akq + 3][arow] = av.w;
        *(float4*)&Bs[bk][bc] = *(const float4*)(Bptr + (size_t)k0 * ldb);
        __syncthreads();
#pragma unroll
        for (int kk = 0; kk < 16; kk++) {
            float4 a4 = *(const float4*)&As[kk][ty << 2];
            float4 b4 = *(const float4*)&Bs[kk][tx << 2];
            float am[4] = {a4.x, a4.y, a4.z, a4.w};
            float bm[4] = {b4.x, b4.y, b4.z, b4.w};
#pragma unroll
            for (int i = 0; i < 4; i++)
#pragma unroll
                for (int j = 0; j < 4; j++) acc[i][j] += am[i] * bm[j];
        }
        __syncthreads();
    }

#pragma unroll
    for (int i = 0; i < 4; i++) {
        int row = row0 + (ty << 2) + i;
        float sc = rowScale ? rowScale[row] : 1.f;
        float r[4];
#pragma unroll
        for (int j = 0; j < 4; j++) {
            float x = acc[i][j] * sc;
            if (bias) x += bias[col0 + (tx << 2) + j];
            if (act == 1) x = fmaxf(x, 0.f);
            r[j] = x;
        }
        *(float4*)(C + (size_t)row * ldc + col0 + (tx << 2)) =
            make_float4(r[0], r[1], r[2], r[3]);
    }
}

// ---------------- s,t = h@a_src, h@a_dst ----------------
__global__ void compute_st_k(const float* __restrict__ h, const float* __restrict__ a, int F,
                             float* __restrict__ s, float* __restrict__ t) {
    __shared__ float r1[256], r2[256];
    int i = blockIdx.x, tid = threadIdx.x;
    float as = 0.f, at = 0.f;
    for (int k = tid; k < F; k += 256) {
        float v = h[(size_t)i * F + k];
        as += v * a[k];
        at += v * a[F + k];
    }
    r1[tid] = as; r2[tid] = at;
    __syncthreads();
    for (int s2 = 128; s2 > 0; s2 >>= 1) {
        if (tid < s2) { r1[tid] += r1[tid + s2]; r2[tid] += r2[tid + s2]; }
        __syncthreads();
    }
    if (tid == 0) { s[i] = r1[0]; t[i] = r2[0]; }
}

// ---------------- per-row masked softmax weights (unnormalized) ----------------
__global__ void attn_rows_k(const float* __restrict__ s, const float* __restrict__ t,
                            const unsigned* __restrict__ mask, float* __restrict__ P,
                            float* __restrict__ invZ) {
    __shared__ float sh_t[NN];
    __shared__ unsigned sh_m[128];
    __shared__ float red[256];
    int i = blockIdx.x, tid = threadIdx.x;
    for (int j = tid; j < NN; j += 256) sh_t[j] = t[j];
    if (tid < 128) sh_m[tid] = mask[i * 128 + tid];
    __syncthreads();

    float si = s[i];
    float mx = -1e30f;
    for (int j = tid; j < NN; j += 256) {
        if ((sh_m[j >> 5] >> (j & 31)) & 1u) {
            float v = si + sh_t[j];
            v = v > 0.f ? v : 0.2f * v;
            mx = fmaxf(mx, v);
        }
    }
    red[tid] = mx;
    __syncthreads();
    for (int s2 = 128; s2 > 0; s2 >>= 1) {
        if (tid < s2) red[tid] = fmaxf(red[tid], red[tid + s2]);
        __syncthreads();
    }
    float m = red[0];
    __syncthreads();

    float sum = 0.f;
    float* Prow = P + (size_t)i * NN;
    for (int j = tid; j < NN; j += 256) {
        float p = 0.f;
        if ((sh_m[j >> 5] >> (j & 31)) & 1u) {
            float v = si + sh_t[j];
            v = v > 0.f ? v : 0.2f * v;
            p = __expf(v - m);
        }
        Prow[j] = p;
        sum += p;
    }
    red[tid] = sum;
    __syncthreads();
    for (int s2 = 128; s2 > 0; s2 >>= 1) {
        if (tid < s2) red[tid] += red[tid + s2];
        __syncthreads();
    }
    if (tid == 0) invZ[i] = 1.f / red[0];
}

// ---------------- GroupNorm (num_groups=1 over the WHOLE tensor, unbiased var) ----------------
__global__ void gn_reduce1_k(const float* __restrict__ h, float* __restrict__ part) {
    __shared__ float r1[256], r2[256];
    int tid = threadIdx.x;
    float s = 0.f, q = 0.f;
    for (size_t idx = (size_t)blockIdx.x * 256 + tid; idx < (size_t)NN * 1536;
         idx += (size_t)2048 * 256) {
        float v = h[idx];
        s += v;
        q += v * v;
    }
    r1[tid] = s; r2[tid] = q;
    __syncthreads();
    for (int s2 = 128; s2 > 0; s2 >>= 1) {
        if (tid < s2) { r1[tid] += r1[tid + s2]; r2[tid] += r2[tid + s2]; }
        __syncthreads();
    }
    if (tid == 0) { part[blockIdx.x] = r1[0]; part[2048 + blockIdx.x] = r2[0]; }
}

__global__ void gn_reduce2_k(const float* __restrict__ part, float* __restrict__ stats) {
    __shared__ double r1[1024], r2[1024];
    int tid = threadIdx.x;
    double s = 0.0, q = 0.0;
    for (int i = tid; i < 2048; i += 1024) { s += part[i]; q += part[2048 + i]; }
    r1[tid] = s; r2[tid] = q;
    __syncthreads();
    for (int s2 = 512; s2 > 0; s2 >>= 1) {
        if (tid < s2) { r1[tid] += r1[tid + s2]; r2[tid] += r2[tid + s2]; }
        __syncthreads();
    }
    if (tid == 0) {
        double n = (double)NN * 1536.0;
        double mu = r1[0] / n;
        double var = (r2[0] - n * mu * mu) / (n - 1.0);
        stats[0] = (float)mu;
        stats[1] = (float)(1.0 / sqrt(var + 1e-5));
    }
}

__global__ void gn_apply_k(float* __restrict__ h, const float* __restrict__ w,
                           const float* __restrict__ b, const float* __restrict__ stats) {
    size_t idx = (size_t)blockIdx.x * 256 + threadIdx.x;
    if (idx < (size_t)NN * 1536) {
        int c = (int)(idx % 1536);
        h[idx] = (h[idx] - stats[0]) * stats[1] * w[c] + b[c];
    }
}

// ---------------- host side ----------------
static void run_sgemm(const float* A, const float* B, float* C, int M, int N, int K,
                      int lda, int ldb, int ldc, const float* bias, const float* rs, int act) {
    dim3 grid(N / 64, M / 64);
    sgemm64_k<<<grid, 256>>>(A, B, C, K, lda, ldb, ldc, bias, rs, act);
}

extern "C" void kernel_launch(void* const* d_in, const int* in_sizes, int n_in,
                              void* d_out, int out_size) {
    const float* x       = (const float*)d_in[0];
    const int*   adj     = (const int*)d_in[1];
    const float* lin1_w  = (const float*)d_in[2];
    const float* lin1_b  = (const float*)d_in[3];
    const float* lin2_w  = (const float*)d_in[4];
    const float* lin2_b  = (const float*)d_in[5];
    const float* conv1_W = (const float*)d_in[6];
    const float* conv1_a = (const float*)d_in[7];
    const float* att_W   = (const float*)d_in[8];
    const float* att_a   = (const float*)d_in[9];
    const float* gn_w    = (const float*)d_in[10];
    const float* gn_b    = (const float*)d_in[11];
    const float* conv2_W = (const float*)d_in[12];
    const float* conv2_a = (const float*)d_in[13];
    float* out = (float*)d_out;

    void* p;
    cudaGetSymbolAddress(&p, g_P);    float* P    = (float*)p;
    cudaGetSymbolAddress(&p, g_hA);   float* hA   = (float*)p;
    cudaGetSymbolAddress(&p, g_out1); float* out1 = (float*)p;
    cudaGetSymbolAddress(&p, g_cat);  float* cat  = (float*)p;
    cudaGetSymbolAddress(&p, g_hB);   float* hB   = (float*)p;
    cudaGetSymbolAddress(&p, g_l1);   float* l1   = (float*)p;
    cudaGetSymbolAddress(&p, g_l2);   float* l2   = (float*)p;
    cudaGetSymbolAddress(&p, g_s);    float* s    = (float*)p;
    cudaGetSymbolAddress(&p, g_t);    float* t    = (float*)p;
    cudaGetSymbolAddress(&p, g_invZ); float* invZ = (float*)p;
    cudaGetSymbolAddress(&p, g_mask); unsigned* mask = (unsigned*)p;
    cudaGetSymbolAddress(&p, g_part); float* part = (float*)p;
    cudaGetSymbolAddress(&p, g_stats);float* stats= (float*)p;

    // adjacency -> bitmask (once per launch; graph replays it, cheap anyway)
    pack_mask_k<<<NN, 128>>>(adj, mask);

    // lin1 + lin2 (with biases, no activation)
    run_sgemm(x,  lin1_w, l1, NN, 64, 128, 128, 64, 64, lin1_b, nullptr, 0);
    run_sgemm(l1, lin2_w, l2, NN, 64, 64,  64,  64, 64, lin2_b, nullptr, 0);

    // ---- GAT conv1 (F=512), then relu ----
    run_sgemm(l2, conv1_W, hA, NN, 512, 64, 64, 512, 512, nullptr, nullptr, 0);
    compute_st_k<<<NN, 256>>>(hA, conv1_a, 512, s, t);
    attn_rows_k<<<NN, 256>>>(s, t, mask, P, invZ);
    run_sgemm(P, hA, out1, NN, 512, NN, NN, 512, 512, nullptr, invZ, 1);

    // ---- 6 attention heads (F=256), elu then relu == relu; concat into g_cat ----
    for (int h = 0; h < 6; h++) {
        run_sgemm(out1, att_W + (size_t)h * 512 * 256, hB, NN, 256, 512, 512, 256, 256,
                  nullptr, nullptr, 0);
        compute_st_k<<<NN, 256>>>(hB, att_a + (size_t)h * 512, 256, s, t);
        attn_rows_k<<<NN, 256>>>(s, t, mask, P, invZ);
        run_sgemm(P, hB, cat + (size_t)h * 256, NN, 256, NN, NN, 256, 1536, nullptr, invZ, 1);
    }

    // ---- GroupNorm(1 group) over all N*1536 elements, unbiased variance ----
    gn_reduce1_k<<<2048, 256>>>(cat, part);
    gn_reduce2_k<<<1, 1024>>>(part, stats);
    {
        size_t total = (size_t)NN * 1536;
        int blocks = (int)((total + 255) / 256);
        gn_apply_k<<<blocks, 256>>>(cat, gn_w, gn_b, stats);
    }

    // ---- GAT conv2 (F=256), no activation, write to d_out ----
    run_sgemm(cat, conv2_W, hB, NN, 256, 1536, 1536, 256, 256, nullptr, nullptr, 0);
    compute_st_k<<<NN, 256>>>(hB, conv2_a, 256, s, t);
    attn_rows_k<<<NN, 256>>>(s, t, mask, P, invZ);
    run_sgemm(P, hB, out, NN, 256, NN, NN, 256, 256, nullptr, invZ, 0);
}

// round 2
// speedup vs baseline: 1.1500x; 1.1500x over previous
#include <cuda_runtime.h>
#include <math.h>

#define NN 4096

// ---------------- scratch (device globals) ----------------
__device__ float g_P[(size_t)NN * NN];        // 64 MB attention weights (unnormalized)
__device__ float g_hA[NN * 512];              // conv1 h
__device__ float g_out1[NN * 512];            // conv1 output
__device__ float g_cat[NN * 1536];            // concatenated head outputs
__device__ float g_hB6[6 * NN * 256];         // all 6 head projections
__device__ float g_hB[NN * 256];              // conv2 h
__device__ float g_l1[NN * 64];
__device__ float g_l2[NN * 64];
__device__ float g_sv[8 * NN];                // s per slot
__device__ float g_tv[8 * NN];                // t per slot
__device__ float g_E[8 * NN];                 // exp(t - maxt)
__device__ float g_Fv[8 * NN];                // exp(0.2(t - maxt))
__device__ unsigned g_maxtKey[8];
__device__ float g_maxt[8];
__device__ float g_invZ[NN];
__device__ unsigned g_mask[NN * 128];
__device__ float g_part[2 * 2048];
__device__ float g_stats[2];

__device__ __forceinline__ unsigned fenc(float f) {
    unsigned u = __float_as_uint(f);
    return (u & 0x80000000u) ? ~u : (u | 0x80000000u);
}
__device__ __forceinline__ float fdec(unsigned k) {
    unsigned u = (k & 0x80000000u) ? (k & 0x7fffffffu) : ~k;
    return __uint_as_float(u);
}

// ---------------- bitmask pack + maxt reset ----------------
__global__ void pack_mask_k(const int* __restrict__ adj, unsigned* __restrict__ mask,
                            unsigned* __restrict__ keys) {
    int i = blockIdx.x;
    int w = threadIdx.x;               // 0..127
    if (i == 0 && w < 8) keys[w] = 0u;
    const int* row = adj + (size_t)i * NN + w * 32;
    unsigned bits = 0;
#pragma unroll
    for (int b = 0; b < 32; b++) bits |= (row[b] > 0 ? 1u : 0u) << b;
    mask[i * 128 + w] = bits;
}

// ---------------- main GEMM: BM=128, BK=16, 256 threads, double-buffered ----------------
// C = A[M x K] * B[K x N]; per-thread 8 x TN microtile. Optional z-batching on B/C.
template <int BN, int TN>
__global__ void __launch_bounds__(256) gemm128_k(
    const float* __restrict__ A, const float* __restrict__ B, float* __restrict__ C,
    int K, int lda, int ldb, int ldc,
    const float* __restrict__ bias, const float* __restrict__ rowScale, int act,
    long strideB, long strideC) {
    __shared__ float As[2][16][128];
    __shared__ float Bs[2][16][BN];

    B += (long)blockIdx.z * strideB;
    C += (long)blockIdx.z * strideC;

    const int tid = threadIdx.x;
    const int tx = tid & 15;           // 16 col-groups
    const int ty = tid >> 4;           // 16 row-groups
    const int row0 = blockIdx.y * 128;
    const int col0 = blockIdx.x * BN;

    // A tile loader indices: 512 float4 / tile, 2 per thread
    int am[2], akq[2];
#pragma unroll
    for (int i = 0; i < 2; i++) {
        int idx = tid + i * 256;
        am[i] = idx >> 2;
        akq[i] = (idx & 3) << 2;
    }
    // B tile loader indices
    constexpr int BCNT = (16 * BN / 4) / 256;   // 1 (BN=64) or 2 (BN=128)
    int bk[BCNT], bn[BCNT];
#pragma unroll
    for (int i = 0; i < BCNT; i++) {
        int idx = tid + i * 256;
        bk[i] = idx / (BN / 4);
        bn[i] = (idx % (BN / 4)) << 2;
    }

    float acc[8][TN];
#pragma unroll
    for (int i = 0; i < 8; i++)
#pragma unroll
        for (int j = 0; j < TN; j++) acc[i][j] = 0.f;

    float4 aR[2];
    float4 bR[BCNT];

    // prologue: tile 0
#pragma unroll
    for (int i = 0; i < 2; i++)
        aR[i] = *(const float4*)(A + (size_t)(row0 + am[i]) * lda + akq[i]);
#pragma unroll
    for (int i = 0; i < BCNT; i++)
        bR[i] = *(const float4*)(B + (size_t)bk[i] * ldb + col0 + bn[i]);
#pragma unroll
    for (int i = 0; i < 2; i++) {
        As[0][akq[i] + 0][am[i]] = aR[i].x;
        As[0][akq[i] + 1][am[i]] = aR[i].y;
        As[0][akq[i] + 2][am[i]] = aR[i].z;
        As[0][akq[i] + 3][am[i]] = aR[i].w;
    }
#pragma unroll
    for (int i = 0; i < BCNT; i++) *(float4*)&Bs[0][bk[i]][bn[i]] = bR[i];
    __syncthreads();

    const int nT = K >> 4;
    for (int t = 0; t < nT; t++) {
        const int buf = t & 1;
        if (t + 1 < nT) {
            const int k0 = (t + 1) << 4;
#pragma unroll
            for (int i = 0; i < 2; i++)
                aR[i] = *(const float4*)(A + (size_t)(row0 + am[i]) * lda + k0 + akq[i]);
#pragma unroll
            for (int i = 0; i < BCNT; i++)
                bR[i] = *(const float4*)(B + (size_t)(k0 + bk[i]) * ldb + col0 + bn[i]);
        }
#pragma unroll
        for (int kk = 0; kk < 16; kk++) {
            float4 a0 = *(const float4*)&As[buf][kk][ty * 8];
            float4 a1 = *(const float4*)&As[buf][kk][ty * 8 + 4];
            float av[8] = {a0.x, a0.y, a0.z, a0.w, a1.x, a1.y, a1.z, a1.w};
            float bv[TN];
            float4 b0 = *(const float4*)&Bs[buf][kk][tx * TN];
            bv[0] = b0.x; bv[1] = b0.y; bv[2] = b0.z; bv[3] = b0.w;
            if (TN == 8) {
                float4 b1 = *(const float4*)&Bs[buf][kk][tx * TN + 4];
                bv[4] = b1.x; bv[5] = b1.y; bv[6] = b1.z; bv[7] = b1.w;
            }
#pragma unroll
            for (int i = 0; i < 8; i++)
#pragma unroll
                for (int j = 0; j < TN; j++) acc[i][j] += av[i] * bv[j];
        }
        if (t + 1 < nT) {
            const int nb = buf ^ 1;
#pragma unroll
            for (int i = 0; i < 2; i++) {
                As[nb][akq[i] + 0][am[i]] = aR[i].x;
                As[nb][akq[i] + 1][am[i]] = aR[i].y;
                As[nb][akq[i] + 2][am[i]] = aR[i].z;
                As[nb][akq[i] + 3][am[i]] = aR[i].w;
            }
#pragma unroll
            for (int i = 0; i < BCNT; i++) *(float4*)&Bs[nb][bk[i]][bn[i]] = bR[i];
            __syncthreads();
        }
    }

    // epilogue
#pragma unroll
    for (int i = 0; i < 8; i++) {
        int row = row0 + ty * 8 + i;
        float sc = rowScale ? rowScale[row] : 1.f;
#pragma unroll
        for (int j4 = 0; j4 < TN; j4 += 4) {
            float r[4];
#pragma unroll
            for (int j = 0; j < 4; j++) {
                float x = acc[i][j4 + j] * sc;
                if (bias) x += bias[col0 + tx * TN + j4 + j];
                if (act == 1) x = fmaxf(x, 0.f);
                r[j] = x;
            }
            *(float4*)(C + (size_t)row * ldc + col0 + tx * TN + j4) =
                make_float4(r[0], r[1], r[2], r[3]);
        }
    }
}

// ---------------- s,t = h@a_src, h@a_dst (batched over heads via blockIdx.y) ----------------
__global__ void st_k(const float* __restrict__ h, long hStride,
                     const float* __restrict__ a, long aStride, int F,
                     float* __restrict__ s, float* __restrict__ t,
                     unsigned* __restrict__ key) {
    __shared__ float r1[256], r2[256];
    int b = blockIdx.y;
    h += (long)b * hStride;
    a += (long)b * aStride;
    int i = blockIdx.x, tid = threadIdx.x;
    float as = 0.f, at = 0.f;
    for (int k = tid; k < F; k += 256) {
        float v = h[(size_t)i * F + k];
        as += v * a[k];
        at += v * a[F + k];
    }
    r1[tid] = as; r2[tid] = at;
    __syncthreads();
    for (int s2 = 128; s2 > 0; s2 >>= 1) {
        if (tid < s2) { r1[tid] += r1[tid + s2]; r2[tid] += r2[tid + s2]; }
        __syncthreads();
    }
    if (tid == 0) {
        s[b * NN + i] = r1[0];
        t[b * NN + i] = r2[0];
        atomicMax(&key[b], fenc(r2[0]));
    }
}

// ---------------- E = exp(t - maxt), F = exp(0.2(t - maxt)) ----------------
__global__ void etf_k(const float* __restrict__ t, const unsigned* __restrict__ key,
                      float* __restrict__ maxt, float* __restrict__ E,
                      float* __restrict__ Fv) {
    int b = blockIdx.y;
    float mt = fdec(key[b]);
    if (blockIdx.x == 0 && threadIdx.x == 0) maxt[b] = mt;
    int j = blockIdx.x * 512 + threadIdx.x;
    float tv = t[b * NN + j] - mt;
    E[b * NN + j] = expf(tv);
    Fv[b * NN + j] = expf(0.2f * tv);
}

// ---------------- per-row masked softmax weights, NO per-element exp ----------------
__global__ void attn_k(const float* __restrict__ s, const float* __restrict__ E,
                       const float* __restrict__ Fv, const float* __restrict__ maxt,
                       const unsigned* __restrict__ mask, float* __restrict__ P,
                       float* __restrict__ invZ) {
    __shared__ float shE[NN];
    __shared__ float shF[NN];
    __shared__ unsigned shm[128];
    __shared__ float red[256];
    int i = blockIdx.x, tid = threadIdx.x;
    for (int j = tid; j < NN; j += 256) { shE[j] = E[j]; shF[j] = Fv[j]; }
    if (tid < 128) shm[tid] = mask[i * 128 + tid];
    __syncthreads();

    float q = s[i] + *maxt;
    float m = fmaxf(q, 0.2f * q);
    float c = expf(q - m);          // positive-branch row factor
    float d = expf(0.2f * q - m);   // negative-branch row factor
    float th = expf(-q);            // branch threshold: E[j] > th  <=>  s_i + t_j > 0

    float sum = 0.f;
    float* Prow = P + (size_t)i * NN;
    for (int j = tid; j < NN; j += 256) {
        float p = 0.f;
        if ((shm[j >> 5] >> (j & 31)) & 1u) {
            float e = shE[j];
            p = (e > th) ? c * e : d * shF[j];
        }
        Prow[j] = p;
        sum += p;
    }
    red[tid] = sum;
    __syncthreads();
    for (int s2 = 128; s2 > 0; s2 >>= 1) {
        if (tid < s2) red[tid] += red[tid + s2];
        __syncthreads();
    }
    if (tid == 0) invZ[i] = 1.f / red[0];
}

// ---------------- GroupNorm (1 group over whole tensor, unbiased var) ----------------
__global__ void gn_reduce1_k(const float* __restrict__ h, float* __restrict__ part) {
    __shared__ float r1[256], r2[256];
    int tid = threadIdx.x;
    float s = 0.f, q = 0.f;
    for (size_t idx = (size_t)blockIdx.x * 256 + tid; idx < (size_t)NN * 1536;
         idx += (size_t)2048 * 256) {
        float v = h[idx];
        s += v;
        q += v * v;
    }
    r1[tid] = s; r2[tid] = q;
    __syncthreads();
    for (int s2 = 128; s2 > 0; s2 >>= 1) {
        if (tid < s2) { r1[tid] += r1[tid + s2]; r2[tid] += r2[tid + s2]; }
        __syncthreads();
    }
    if (tid == 0) { part[blockIdx.x] = r1[0]; part[2048 + blockIdx.x] = r2[0]; }
}

__global__ void gn_reduce2_k(const float* __restrict__ part, float* __restrict__ stats) {
    __shared__ double r1[1024], r2[1024];
    int tid = threadIdx.x;
    double s = 0.0, q = 0.0;
    for (int i = tid; i < 2048; i += 1024) { s += part[i]; q += part[2048 + i]; }
    r1[tid] = s; r2[tid] = q;
    __syncthreads();
    for (int s2 = 512; s2 > 0; s2 >>= 1) {
        if (tid < s2) { r1[tid] += r1[tid + s2]; r2[tid] += r2[tid + s2]; }
        __syncthreads();
    }
    if (tid == 0) {
        double n = (double)NN * 1536.0;
        double mu = r1[0] / n;
        double var = (r2[0] - n * mu * mu) / (n - 1.0);
        stats[0] = (float)mu;
        stats[1] = (float)(1.0 / sqrt(var + 1e-5));
    }
}

__global__ void gn_apply_k(float* __restrict__ h, const float* __restrict__ w,
                           const float* __restrict__ b, const float* __restrict__ stats) {
    size_t idx = (size_t)blockIdx.x * 256 + threadIdx.x;
    if (idx < (size_t)NN * 1536) {
        int c = (int)(idx % 1536);
        h[idx] = (h[idx] - stats[0]) * stats[1] * w[c] + b[c];
    }
}

// ---------------- host side ----------------
extern "C" void kernel_launch(void* const* d_in, const int* in_sizes, int n_in,
                              void* d_out, int out_size) {
    const float* x       = (const float*)d_in[0];
    const int*   adj     = (const int*)d_in[1];
    const float* lin1_w  = (const float*)d_in[2];
    const float* lin1_b  = (const float*)d_in[3];
    const float* lin2_w  = (const float*)d_in[4];
    const float* lin2_b  = (const float*)d_in[5];
    const float* conv1_W = (const float*)d_in[6];
    const float* conv1_a = (const float*)d_in[7];
    const float* att_W   = (const float*)d_in[8];
    const float* att_a   = (const float*)d_in[9];
    const float* gn_w    = (const float*)d_in[10];
    const float* gn_b    = (const float*)d_in[11];
    const float* conv2_W = (const float*)d_in[12];
    const float* conv2_a = (const float*)d_in[13];
    float* out = (float*)d_out;

    void* p;
    cudaGetSymbolAddress(&p, g_P);       float* P    = (float*)p;
    cudaGetSymbolAddress(&p, g_hA);      float* hA   = (float*)p;
    cudaGetSymbolAddress(&p, g_out1);    float* out1 = (float*)p;
    cudaGetSymbolAddress(&p, g_cat);     float* cat  = (float*)p;
    cudaGetSymbolAddress(&p, g_hB6);     float* hB6  = (float*)p;
    cudaGetSymbolAddress(&p, g_hB);      float* hB   = (float*)p;
    cudaGetSymbolAddress(&p, g_l1);      float* l1   = (float*)p;
    cudaGetSymbolAddress(&p, g_l2);      float* l2   = (float*)p;
    cudaGetSymbolAddress(&p, g_sv);      float* sv   = (float*)p;
    cudaGetSymbolAddress(&p, g_tv);      float* tv   = (float*)p;
    cudaGetSymbolAddress(&p, g_E);       float* E    = (float*)p;
    cudaGetSymbolAddress(&p, g_Fv);      float* Fv   = (float*)p;
    cudaGetSymbolAddress(&p, g_maxtKey); unsigned* keys = (unsigned*)p;
    cudaGetSymbolAddress(&p, g_maxt);    float* maxt = (float*)p;
    cudaGetSymbolAddress(&p, g_invZ);    float* invZ = (float*)p;
    cudaGetSymbolAddress(&p, g_mask);    unsigned* mask = (unsigned*)p;
    cudaGetSymbolAddress(&p, g_part);    float* part = (float*)p;
    cudaGetSymbolAddress(&p, g_stats);   float* stats = (float*)p;

    pack_mask_k<<<NN, 128>>>(adj, mask, keys);

    // lin1 + lin2
    gemm128_k<64, 4><<<dim3(1, 32, 1), 256>>>(x,  lin1_w, l1, 128, 128, 64, 64,
                                              lin1_b, nullptr, 0, 0, 0);
    gemm128_k<64, 4><<<dim3(1, 32, 1), 256>>>(l1, lin2_w, l2, 64, 64, 64, 64,
                                              lin2_b, nullptr, 0, 0, 0);

    // ---- GAT conv1 (F=512), slot 0 ----
    gemm128_k<128, 8><<<dim3(4, 32, 1), 256>>>(l2, conv1_W, hA, 64, 64, 512, 512,
                                               nullptr, nullptr, 0, 0, 0);
    st_k<<<dim3(NN, 1), 256>>>(hA, 0, conv1_a, 0, 512, sv, tv, keys);
    etf_k<<<dim3(8, 1), 512>>>(tv, keys, maxt, E, Fv);
    attn_k<<<NN, 256>>>(sv, E, Fv, maxt, mask, P, invZ);
    gemm128_k<128, 8><<<dim3(4, 32, 1), 256>>>(P, hA, out1, NN, NN, 512, 512,
                                               nullptr, invZ, 1, 0, 0);

    // ---- 6 attention heads (F=256), slots 1..6 ----
    gemm128_k<64, 4><<<dim3(4, 32, 6), 256>>>(out1, att_W, hB6, 512, 512, 256, 256,
                                              nullptr, nullptr, 0,
                                              (long)512 * 256, (long)NN * 256);
    st_k<<<dim3(NN, 6), 256>>>(hB6, (long)NN * 256, att_a, 512, 256,
                               sv + NN, tv + NN, keys + 1);
    etf_k<<<dim3(8, 6), 512>>>(tv + NN, keys + 1, maxt + 1, E + NN, Fv + NN);
    for (int h = 0; h < 6; h++) {
        attn_k<<<NN, 256>>>(sv + (1 + h) * NN, E + (1 + h) * NN, Fv + (1 + h) * NN,
                            maxt + 1 + h, mask, P, invZ);
        gemm128_k<64, 4><<<dim3(4, 32, 1), 256>>>(P, hB6 + (size_t)h * NN * 256,
                                                  cat + (size_t)h * 256,
                                                  NN, NN, 256, 1536,
                                                  nullptr, invZ, 1, 0, 0);
    }

    // ---- GroupNorm ----
    gn_reduce1_k<<<2048, 256>>>(cat, part);
    gn_reduce2_k<<<1, 1024>>>(part, stats);
    {
        size_t total = (size_t)NN * 1536;
        int blocks = (int)((total + 255) / 256);
        gn_apply_k<<<blocks, 256>>>(cat, gn_w, gn_b, stats);
    }

    // ---- GAT conv2 (F=256), slot 7 ----
    gemm128_k<64, 4><<<dim3(4, 32, 1), 256>>>(cat, conv2_W, hB, 1536, 1536, 256, 256,
                                              nullptr, nullptr, 0, 0, 0);
    st_k<<<dim3(NN, 1), 256>>>(hB, 0, conv2_a, 0, 256, sv + 7 * NN, tv + 7 * NN, keys + 7);
    etf_k<<<dim3(8, 1), 512>>>(tv + 7 * NN, keys + 7, maxt + 7, E + 7 * NN, Fv + 7 * NN);
    attn_k<<<NN, 256>>>(sv + 7 * NN, E + 7 * NN, Fv + 7 * NN, maxt + 7, mask, P, invZ);
    gemm128_k<64, 4><<<dim3(4, 32, 1), 256>>>(P, hB, out, NN, NN, 256, 256,
                                              nullptr, invZ, 0, 0, 0);
}

// round 4
// speedup vs baseline: 2.5617x; 2.2276x over previous
#include <cuda_runtime.h>
#include <cuda_bf16.h>
#include <math.h>

#define NN 4096

// ---------------- scratch (device globals) ----------------
__device__ __nv_bfloat16 g_Phi[(size_t)NN * NN];
__device__ __nv_bfloat16 g_Plo[(size_t)NN * NN];
__device__ float g_hA[NN * 512];
__device__ __nv_bfloat16 g_hAhi[NN * 512];
__device__ __nv_bfloat16 g_hAlo[NN * 512];
__device__ float g_out1[NN * 512];
__device__ __nv_bfloat16 g_out1hi[NN * 512];
__device__ __nv_bfloat16 g_out1lo[NN * 512];
__device__ float g_cat[NN * 1536];
__device__ __nv_bfloat16 g_cathi[NN * 1536];
__device__ __nv_bfloat16 g_catlo[NN * 1536];
__device__ float g_hB6[6 * NN * 256];
__device__ __nv_bfloat16 g_hB6hi[6 * NN * 256];
__device__ __nv_bfloat16 g_hB6lo[6 * NN * 256];
__device__ float g_hB[NN * 256];
__device__ __nv_bfloat16 g_hBhi[NN * 256];
__device__ __nv_bfloat16 g_hBlo[NN * 256];
__device__ __nv_bfloat16 g_attWhi[6 * 512 * 256];
__device__ __nv_bfloat16 g_attWlo[6 * 512 * 256];
__device__ __nv_bfloat16 g_c2Whi[1536 * 256];
__device__ __nv_bfloat16 g_c2Wlo[1536 * 256];
__device__ float g_l1[NN * 64];
__device__ float g_l2[NN * 64];
__device__ float g_sv[8 * NN];
__device__ float g_tv[8 * NN];
__device__ float g_E[8 * NN];
__device__ float g_Fv[8 * NN];
__device__ unsigned g_maxtKey[8];
__device__ float g_maxt[8];
__device__ float g_invZ[NN];
__device__ unsigned g_mask[NN * 128];
__device__ float g_part[2 * 2048];
__device__ float g_stats[2];

__device__ __forceinline__ unsigned fenc(float f) {
    unsigned u = __float_as_uint(f);
    return (u & 0x80000000u) ? ~u : (u | 0x80000000u);
}
__device__ __forceinline__ float fdec(unsigned k) {
    unsigned u = (k & 0x80000000u) ? (k & 0x7fffffffu) : ~k;
    return __uint_as_float(u);
}
__device__ __forceinline__ unsigned sptr(const void* p) {
    return (unsigned)__cvta_generic_to_shared(p);
}
__device__ __forceinline__ void cpasync16(unsigned s, const void* g) {
    asm volatile("cp.async.cg.shared.global [%0], [%1], 16;\n" :: "r"(s), "l"(g));
}
__device__ __forceinline__ void ldm_x4(unsigned a, unsigned& r0, unsigned& r1,
                                       unsigned& r2, unsigned& r3) {
    asm volatile("ldmatrix.sync.aligned.m8n8.x4.shared.b16 {%0,%1,%2,%3}, [%4];"
                 : "=r"(r0), "=r"(r1), "=r"(r2), "=r"(r3) : "r"(a));
}
__device__ __forceinline__ void ldm_x4t(unsigned a, unsigned& r0, unsigned& r1,
                                        unsigned& r2, unsigned& r3) {
    asm volatile("ldmatrix.sync.aligned.m8n8.x4.trans.shared.b16 {%0,%1,%2,%3}, [%4];"
                 : "=r"(r0), "=r"(r1), "=r"(r2), "=r"(r3) : "r"(a));
}
__device__ __forceinline__ void mma16816(float* c, const unsigned* a, const unsigned* b) {
    asm volatile(
        "mma.sync.aligned.m16n8k16.row.col.f32.bf16.bf16.f32 "
        "{%0,%1,%2,%3},{%4,%5,%6,%7},{%8,%9},{%0,%1,%2,%3};"
        : "+f"(c[0]), "+f"(c[1]), "+f"(c[2]), "+f"(c[3])
        : "r"(a[0]), "r"(a[1]), "r"(a[2]), "r"(a[3]), "r"(b[0]), "r"(b[1]));
}
__device__ __forceinline__ void split1(float v, __nv_bfloat16& hi, __nv_bfloat16& lo) {
    hi = __float2bfloat16(v);
    lo = __float2bfloat16(v - __bfloat162float(hi));
}

// ---------------- bitmask pack + maxt reset ----------------
__global__ void pack_mask_k(const int* __restrict__ adj, unsigned* __restrict__ mask,
                            unsigned* __restrict__ keys) {
    int i = blockIdx.x;
    int w = threadIdx.x;
    if (i == 0 && w < 8) keys[w] = 0u;
    const int* row = adj + (size_t)i * NN + w * 32;
    unsigned bits = 0;
#pragma unroll
    for (int b = 0; b < 32; b++) bits |= (row[b] > 0 ? 1u : 0u) << b;
    mask[i * 128 + w] = bits;
}

// ---------------- fp32 GEMM for the small projections ----------------
template <int BN, int TN>
__global__ void __launch_bounds__(256) gemm128_k(
    const float* __restrict__ A, const float* __restrict__ B, float* __restrict__ C,
    int K, int lda, int ldb, int ldc,
    const float* __restrict__ bias, int act) {
    __shared__ float As[2][16][128];
    __shared__ float Bs[2][16][BN];
    const int tid = threadIdx.x;
    const int tx = tid & 15, ty = tid >> 4;
    const int row0 = blockIdx.y * 128, col0 = blockIdx.x * BN;
    int am[2], akq[2];
#pragma unroll
    for (int i = 0; i < 2; i++) {
        int idx = tid + i * 256;
        am[i] = idx >> 2;
        akq[i] = (idx & 3) << 2;
    }
    constexpr int BCNT = (16 * BN / 4) / 256;
    int bk[BCNT], bn[BCNT];
#pragma unroll
    for (int i = 0; i < BCNT; i++) {
        int idx = tid + i * 256;
        bk[i] = idx / (BN / 4);
        bn[i] = (idx % (BN / 4)) << 2;
    }
    float acc[8][TN];
#pragma unroll
    for (int i = 0; i < 8; i++)
#pragma unroll
        for (int j = 0; j < TN; j++) acc[i][j] = 0.f;
    float4 aR[2];
    float4 bR[BCNT];
#pragma unroll
    for (int i = 0; i < 2; i++)
        aR[i] = *(const float4*)(A + (size_t)(row0 + am[i]) * lda + akq[i]);
#pragma unroll
    for (int i = 0; i < BCNT; i++)
        bR[i] = *(const float4*)(B + (size_t)bk[i] * ldb + col0 + bn[i]);
#pragma unroll
    for (int i = 0; i < 2; i++) {
        As[0][akq[i] + 0][am[i]] = aR[i].x;
        As[0][akq[i] + 1][am[i]] = aR[i].y;
        As[0][akq[i] + 2][am[i]] = aR[i].z;
        As[0][akq[i] + 3][am[i]] = aR[i].w;
    }
#pragma unroll
    for (int i = 0; i < BCNT; i++) *(float4*)&Bs[0][bk[i]][bn[i]] = bR[i];
    __syncthreads();
    const int nT = K >> 4;
    for (int t = 0; t < nT; t++) {
        const int buf = t & 1;
        if (t + 1 < nT) {
            const int k0 = (t + 1) << 4;
#pragma unroll
            for (int i = 0; i < 2; i++)
                aR[i] = *(const float4*)(A + (size_t)(row0 + am[i]) * lda + k0 + akq[i]);
#pragma unroll
            for (int i = 0; i < BCNT; i++)
                bR[i] = *(const float4*)(B + (size_t)(k0 + bk[i]) * ldb + col0 + bn[i]);
        }
#pragma unroll
        for (int kk = 0; kk < 16; kk++) {
            float4 a0 = *(const float4*)&As[buf][kk][ty * 8];
            float4 a1 = *(const float4*)&As[buf][kk][ty * 8 + 4];
            float av[8] = {a0.x, a0.y, a0.z, a0.w, a1.x, a1.y, a1.z, a1.w};
            float bv[TN];
            float4 b0 = *(const float4*)&Bs[buf][kk][tx * TN];
            bv[0] = b0.x; bv[1] = b0.y; bv[2] = b0.z; bv[3] = b0.w;
            if (TN == 8) {
                float4 b1 = *(const float4*)&Bs[buf][kk][tx * TN + 4];
                bv[4] = b1.x; bv[5] = b1.y; bv[6] = b1.z; bv[7] = b1.w;
            }
#pragma unroll
            for (int i = 0; i < 8; i++)
#pragma unroll
                for (int j = 0; j < TN; j++) acc[i][j] += av[i] * bv[j];
        }
        if (t + 1 < nT) {
            const int nb = buf ^ 1;
#pragma unroll
            for (int i = 0; i < 2; i++) {
                As[nb][akq[i] + 0][am[i]] = aR[i].x;
                As[nb][akq[i] + 1][am[i]] = aR[i].y;
                As[nb][akq[i] + 2][am[i]] = aR[i].z;
                As[nb][akq[i] + 3][am[i]] = aR[i].w;
            }
#pragma unroll
            for (int i = 0; i < BCNT; i++) *(float4*)&Bs[nb][bk[i]][bn[i]] = bR[i];
            __syncthreads();
        }
    }
#pragma unroll
    for (int i = 0; i < 8; i++) {
        int row = row0 + ty * 8 + i;
#pragma unroll
        for (int j4 = 0; j4 < TN; j4 += 4) {
            float r[4];
#pragma unroll
            for (int j = 0; j < 4; j++) {
                float x = acc[i][j4 + j];
                if (bias) x += bias[col0 + tx * TN + j4 + j];
                if (act == 1) x = fmaxf(x, 0.f);
                r[j] = x;
            }
            *(float4*)(C + (size_t)row * ldc + col0 + tx * TN + j4) =
                make_float4(r[0], r[1], r[2], r[3]);
        }
    }
}

// ---------------- 3xBF16 tensor-core GEMM ----------------
// C[M x N] = (Ahi+Alo) @ (Bhi+Blo), fp32 accum via hi*hi + lo*hi + hi*lo.
// BM = MT*32 (warp grid 2x4, warp tile (MT*16) x 32), BN=128, BK=32.
template <int MT>
__global__ void __launch_bounds__(256) mma3_k(
    const __nv_bfloat16* __restrict__ Ahi, const __nv_bfloat16* __restrict__ Alo,
    const __nv_bfloat16* __restrict__ Bhi, const __nv_bfloat16* __restrict__ Blo,
    float* __restrict__ C, __nv_bfloat16* __restrict__ Chi, __nv_bfloat16* __restrict__ Clo,
    int K, int lda, int ldb, int ldc,
    const float* __restrict__ rowScale, int act,
    long strideBz, long strideCz) {
    constexpr int BM = MT * 32;
    constexpr int ABYTES = BM * 128;     // BM rows x (32 hi | 32 lo) bf16 = 128B/row
    constexpr int BBYTES = 32 * 512;     // 32 k-rows x (128 hi | 128 lo) bf16 = 512B/row
    constexpr int LA = BM / 32;          // iterations so LA*256 threads cover BM*8 chunks

    extern __shared__ __align__(16) char smraw[];
    unsigned aBase = sptr(smraw);
    unsigned bBase = aBase + 2 * ABYTES;

    Bhi += (long)blockIdx.z * strideBz;
    Blo += (long)blockIdx.z * strideBz;
    long cz = (long)blockIdx.z * strideCz;

    const int tid = threadIdx.x;
    const int w = tid >> 5, lane = tid & 31;
    const int wm = w >> 2, wn = w & 3;
    const int row0 = blockIdx.y * BM, col0 = blockIdx.x * 128;
    const int nT = K >> 5;

    auto loadTile = [&](int buf, int k0) {
        // A tile: BM rows, 8 chunks of 16B each (4 hi + 4 lo)  => BM*8 total chunks
#pragma unroll
        for (int i = 0; i < LA; i++) {
            int idx = i * 256 + tid;                 // 0 .. BM*8-1
            int plane = idx >= BM * 4 ? 1 : 0;
            int ii = idx - plane * BM * 4;           // 0 .. BM*4-1
            int r = ii >> 2, c4 = ii & 3;
            const __nv_bfloat16* g =
                (plane ? Alo : Ahi) + (size_t)(row0 + r) * lda + k0 + c4 * 8;
            int c = c4 + plane * 4;
            unsigned s = aBase + buf * ABYTES + r * 128 + ((c ^ (r & 7)) << 4);
            cpasync16(s, g);
        }
        // B tile: 32 k-rows x 32 chunks (16 hi + 16 lo) = 1024 chunks
#pragma unroll
        for (int i = 0; i < 4; i++) {
            int idx = i * 256 + tid;
            int plane = idx >> 9;
            int ii = idx & 511;
            int k = ii >> 4, c16 = ii & 15;
            const __nv_bfloat16* g =
                (plane ? Blo : Bhi) + (size_t)(k0 + k) * ldb + col0 + c16 * 8;
            int c = c16 + plane * 16;
            int p = (c & 24) | ((c ^ k) & 7);
            unsigned s = bBase + buf * BBYTES + k * 512 + (p << 4);
            cpasync16(s, g);
        }
    };

    float acc[MT][4][4];
#pragma unroll
    for (int m = 0; m < MT; m++)
#pragma unroll
        for (int n = 0; n < 4; n++)
#pragma unroll
            for (int q = 0; q < 4; q++) acc[m][n][q] = 0.f;

    loadTile(0, 0);
    asm volatile("cp.async.commit_group;\n" ::);

    for (int t = 0; t < nT; t++) {
        asm volatile("cp.async.wait_group 0;\n" ::);
        __syncthreads();
        if (t + 1 < nT) {
            loadTile((t + 1) & 1, (t + 1) * 32);
            asm volatile("cp.async.commit_group;\n" ::);
        }
        const int buf = t & 1;
#pragma unroll
        for (int ks = 0; ks < 2; ks++) {
            unsigned ah[MT][4], al[MT][4], bh[4][2], bl[4][2];
#pragma unroll
            for (int mt = 0; mt < MT; mt++) {
                int rA = wm * MT * 16 + mt * 16 + (lane & 15);
                int ck = ks * 2 + (lane >> 4);
                unsigned base = aBase + buf * ABYTES + rA * 128;
                ldm_x4(base + ((ck ^ (rA & 7)) << 4),
                       ah[mt][0], ah[mt][1], ah[mt][2], ah[mt][3]);
                ldm_x4(base + (((ck + 4) ^ (rA & 7)) << 4),
                       al[mt][0], al[mt][1], al[mt][2], al[mt][3]);
            }
#pragma unroll
            for (int np = 0; np < 2; np++) {
                int kr = ks * 16 + (lane & 15);
                int cb = wn * 4 + np * 2 + (lane >> 4);
                unsigned base = bBase + buf * BBYTES + kr * 512;
                int ph = (cb & 24) | ((cb ^ kr) & 7);
                ldm_x4t(base + (ph << 4), bh[2 * np][0], bh[2 * np][1],
                        bh[2 * np + 1][0], bh[2 * np + 1][1]);
                int cl = cb + 16;
                int pl = (cl & 24) | ((cl ^ kr) & 7);
                ldm_x4t(base + (pl << 4), bl[2 * np][0], bl[2 * np][1],
                        bl[2 * np + 1][0], bl[2 * np + 1][1]);
            }
#pragma unroll
            for (int mt = 0; mt < MT; mt++)
#pragma unroll
                for (int nt = 0; nt < 4; nt++) {
                    mma16816(acc[mt][nt], ah[mt], bh[nt]);
                    mma16816(acc[mt][nt], al[mt], bh[nt]);
                    mma16816(acc[mt][nt], ah[mt], bl[nt]);
                }
        }
    }

    // epilogue
#pragma unroll
    for (int mt = 0; mt < MT; mt++) {
        int r1 = row0 + wm * MT * 16 + mt * 16 + (lane >> 2);
        int r2 = r1 + 8;
        float s1 = rowScale ? rowScale[r1] : 1.f;
        float s2 = rowScale ? rowScale[r2] : 1.f;
#pragma unroll
        for (int nt = 0; nt < 4; nt++) {
            int cidx = col0 + wn * 32 + nt * 8 + (lane & 3) * 2;
            float v0 = acc[mt][nt][0] * s1, v1 = acc[mt][nt][1] * s1;
            float v2 = acc[mt][nt][2] * s2, v3 = acc[mt][nt][3] * s2;
            if (act == 1) {
                v0 = fmaxf(v0, 0.f); v1 = fmaxf(v1, 0.f);
                v2 = fmaxf(v2, 0.f); v3 = fmaxf(v3, 0.f);
            }
            if (C) {
                *(float2*)(C + cz + (size_t)r1 * ldc + cidx) = make_float2(v0, v1);
                *(float2*)(C + cz + (size_t)r2 * ldc + cidx) = make_float2(v2, v3);
            }
            if (Chi) {
                __nv_bfloat162 h, l;
                split1(v0, h.x, l.x); split1(v1, h.y, l.y);
                *(__nv_bfloat162*)(Chi + cz + (size_t)r1 * ldc + cidx) = h;
                *(__nv_bfloat162*)(Clo + cz + (size_t)r1 * ldc + cidx) = l;
                split1(v2, h.x, l.x); split1(v3, h.y, l.y);
                *(__nv_bfloat162*)(Chi + cz + (size_t)r2 * ldc + cidx) = h;
                *(__nv_bfloat162*)(Clo + cz + (size_t)r2 * ldc + cidx) = l;
            }
        }
    }
}

// ---------------- split fp32 -> bf16 hi/lo planes ----------------
__global__ void split_k(const float* __restrict__ x, __nv_bfloat16* __restrict__ hi,
                        __nv_bfloat16* __restrict__ lo, int n) {
    int i = blockIdx.x * 256 + threadIdx.x;
    if (i < n) {
        __nv_bfloat16 h, l;
        split1(x[i], h, l);
        hi[i] = h; lo[i] = l;
    }
}

// ---------------- s,t ----------------
__global__ void st_k(const float* __restrict__ h, long hStride,
                     const float* __restrict__ a, long aStride, int F,
                     float* __restrict__ s, float* __restrict__ t,
                     unsigned* __restrict__ key) {
    __shared__ float r1[256], r2[256];
    int b = blockIdx.y;
    h += (long)b * hStride;
    a += (long)b * aStride;
    int i = blockIdx.x, tid = threadIdx.x;
    float as = 0.f, at = 0.f;
    for (int k = tid; k < F; k += 256) {
        float v = h[(size_t)i * F + k];
        as += v * a[k];
        at += v * a[F + k];
    }
    r1[tid] = as; r2[tid] = at;
    __syncthreads();
    for (int s2 = 128; s2 > 0; s2 >>= 1) {
        if (tid < s2) { r1[tid] += r1[tid + s2]; r2[tid] += r2[tid + s2]; }
        __syncthreads();
    }
    if (tid == 0) {
        s[b * NN + i] = r1[0];
        t[b * NN + i] = r2[0];
        atomicMax(&key[b], fenc(r2[0]));
    }
}

__global__ void etf_k(const float* __restrict__ t, const unsigned* __restrict__ key,
                      float* __restrict__ maxt, float* __restrict__ E,
                      float* __restrict__ Fv) {
    int b = blockIdx.y;
    float mt = fdec(key[b]);
    if (blockIdx.x == 0 && threadIdx.x == 0) maxt[b] = mt;
    int j = blockIdx.x * 512 + threadIdx.x;
    float tv = t[b * NN + j] - mt;
    E[b * NN + j] = expf(tv);
    Fv[b * NN + j] = expf(0.2f * tv);
}

// ---------------- per-row masked softmax weights -> bf16 hi/lo planes ----------------
__global__ void attn_k(const float* __restrict__ s, const float* __restrict__ E,
                       const float* __restrict__ Fv, const float* __restrict__ maxt,
                       const unsigned* __restrict__ mask,
                       __nv_bfloat16* __restrict__ Phi, __nv_bfloat16* __restrict__ Plo,
                       float* __restrict__ invZ) {
    __shared__ float shE[NN];
    __shared__ float shF[NN];
    __shared__ unsigned shm[128];
    __shared__ float red[256];
    int i = blockIdx.x, tid = threadIdx.x;
    for (int j = tid; j < NN; j += 256) { shE[j] = E[j]; shF[j] = Fv[j]; }
    if (tid < 128) shm[tid] = mask[i * 128 + tid];
    __syncthreads();

    float q = s[i] + *maxt;
    float m = fmaxf(q, 0.2f * q);
    float c = expf(q - m);
    float d = expf(0.2f * q - m);
    float th = expf(-q);

    float sum = 0.f;
    __nv_bfloat16* PhiRow = Phi + (size_t)i * NN;
    __nv_bfloat16* PloRow = Plo + (size_t)i * NN;
    for (int j0 = tid * 2; j0 < NN; j0 += 512) {
        unsigned mw = shm[j0 >> 5];
        float p0 = 0.f, p1 = 0.f;
        if ((mw >> (j0 & 31)) & 1u) {
            float e = shE[j0];
            p0 = (e > th) ? c * e : d * shF[j0];
        }
        if ((mw >> ((j0 + 1) & 31)) & 1u) {
            float e = shE[j0 + 1];
            p1 = (e > th) ? c * e : d * shF[j0 + 1];
        }
        sum += p0 + p1;
        __nv_bfloat162 h, l;
        split1(p0, h.x, l.x);
        split1(p1, h.y, l.y);
        *(__nv_bfloat162*)(PhiRow + j0) = h;
        *(__nv_bfloat162*)(PloRow + j0) = l;
    }
    red[tid] = sum;
    __syncthreads();
    for (int s2 = 128; s2 > 0; s2 >>= 1) {
        if (tid < s2) red[tid] += red[tid + s2];
        __syncthreads();
    }
    if (tid == 0) invZ[i] = 1.f / red[0];
}

// ---------------- GroupNorm ----------------
__global__ void gn_reduce1_k(const float* __restrict__ h, float* __restrict__ part) {
    __shared__ float r1[256], r2[256];
    int tid = threadIdx.x;
    float s = 0.f, q = 0.f;
    for (size_t idx = (size_t)blockIdx.x * 256 + tid; idx < (size_t)NN * 1536;
         idx += (size_t)2048 * 256) {
        float v = h[idx];
        s += v;
        q += v * v;
    }
    r1[tid] = s; r2[tid] = q;
    __syncthreads();
    for (int s2 = 128; s2 > 0; s2 >>= 1) {
        if (tid < s2) { r1[tid] += r1[tid + s2]; r2[tid] += r2[tid + s2]; }
        __syncthreads();
    }
    if (tid == 0) { part[blockIdx.x] = r1[0]; part[2048 + blockIdx.x] = r2[0]; }
}

__global__ void gn_reduce2_k(const float* __restrict__ part, float* __restrict__ stats) {
    __shared__ double r1[1024], r2[1024];
    int tid = threadIdx.x;
    double s = 0.0, q = 0.0;
    for (int i = tid; i < 2048; i += 1024) { s += part[i]; q += part[2048 + i]; }
    r1[tid] = s; r2[tid] = q;
    __syncthreads();
    for (int s2 = 512; s2 > 0; s2 >>= 1) {
        if (tid < s2) { r1[tid] += r1[tid + s2]; r2[tid] += r2[tid + s2]; }
        __syncthreads();
    }
    if (tid == 0) {
        double n = (double)NN * 1536.0;
        double mu = r1[0] / n;
        double var = (r2[0] - n * mu * mu) / (n - 1.0);
        stats[0] = (float)mu;
        stats[1] = (float)(1.0 / sqrt(var + 1e-5));
    }
}

__global__ void gn_apply_k(const float* __restrict__ h, const float* __restrict__ w,
                           const float* __restrict__ b, const float* __restrict__ stats,
                           __nv_bfloat16* __restrict__ hi, __nv_bfloat16* __restrict__ lo) {
    size_t idx = (size_t)blockIdx.x * 256 + threadIdx.x;
    if (idx < (size_t)NN * 1536) {
        int c = (int)(idx % 1536);
        float v = (h[idx] - stats[0]) * stats[1] * w[c] + b[c];
        __nv_bfloat16 hh, ll;
        split1(v, hh, ll);
        hi[idx] = hh; lo[idx] = ll;
    }
}

// ---------------- host ----------------
extern "C" void kernel_launch(void* const* d_in, const int* in_sizes, int n_in,
                              void* d_out, int out_size) {
    const float* x       = (const float*)d_in[0];
    const int*   adj     = (const int*)d_in[1];
    const float* lin1_w  = (const float*)d_in[2];
    const float* lin1_b  = (const float*)d_in[3];
    const float* lin2_w  = (const float*)d_in[4];
    const float* lin2_b  = (const float*)d_in[5];
    const float* conv1_W = (const float*)d_in[6];
    const float* conv1_a = (const float*)d_in[7];
    const float* att_W   = (const float*)d_in[8];
    const float* att_a   = (const float*)d_in[9];
    const float* gn_w    = (const float*)d_in[10];
    const float* gn_b    = (const float*)d_in[11];
    const float* conv2_W = (const float*)d_in[12];
    const float* conv2_a = (const float*)d_in[13];
    float* out = (float*)d_out;

    void* p;
    cudaGetSymbolAddress(&p, g_Phi);    __nv_bfloat16* Phi = (__nv_bfloat16*)p;
    cudaGetSymbolAddress(&p, g_Plo);    __nv_bfloat16* Plo = (__nv_bfloat16*)p;
    cudaGetSymbolAddress(&p, g_hA);     float* hA = (float*)p;
    cudaGetSymbolAddress(&p, g_hAhi);   __nv_bfloat16* hAhi = (__nv_bfloat16*)p;
    cudaGetSymbolAddress(&p, g_hAlo);   __nv_bfloat16* hAlo = (__nv_bfloat16*)p;
    cudaGetSymbolAddress(&p, g_out1);   float* out1 = (float*)p;
    cudaGetSymbolAddress(&p, g_out1hi); __nv_bfloat16* out1hi = (__nv_bfloat16*)p;
    cudaGetSymbolAddress(&p, g_out1lo); __nv_bfloat16* out1lo = (__nv_bfloat16*)p;
    cudaGetSymbolAddress(&p, g_cat);    float* cat = (float*)p;
    cudaGetSymbolAddress(&p, g_cathi);  __nv_bfloat16* cathi = (__nv_bfloat16*)p;
    cudaGetSymbolAddress(&p, g_catlo);  __nv_bfloat16* catlo = (__nv_bfloat16*)p;
    cudaGetSymbolAddress(&p, g_hB6);    float* hB6 = (float*)p;
    cudaGetSymbolAddress(&p, g_hB6hi);  __nv_bfloat16* hB6hi = (__nv_bfloat16*)p;
    cudaGetSymbolAddress(&p, g_hB6lo);  __nv_bfloat16* hB6lo = (__nv_bfloat16*)p;
    cudaGetSymbolAddress(&p, g_hB);     float* hB = (float*)p;
    cudaGetSymbolAddress(&p, g_hBhi);   __nv_bfloat16* hBhi = (__nv_bfloat16*)p;
    cudaGetSymbolAddress(&p, g_hBlo);   __nv_bfloat16* hBlo = (__nv_bfloat16*)p;
    cudaGetSymbolAddress(&p, g_attWhi); __nv_bfloat16* attWhi = (__nv_bfloat16*)p;
    cudaGetSymbolAddress(&p, g_attWlo); __nv_bfloat16* attWlo = (__nv_bfloat16*)p;
    cudaGetSymbolAddress(&p, g_c2Whi);  __nv_bfloat16* c2Whi = (__nv_bfloat16*)p;
    cudaGetSymbolAddress(&p, g_c2Wlo);  __nv_bfloat16* c2Wlo = (__nv_bfloat16*)p;
    cudaGetSymbolAddress(&p, g_l1);     float* l1 = (float*)p;
    cudaGetSymbolAddress(&p, g_l2);     float* l2 = (float*)p;
    cudaGetSymbolAddress(&p, g_sv);     float* sv = (float*)p;
    cudaGetSymbolAddress(&p, g_tv);     float* tv = (float*)p;
    cudaGetSymbolAddress(&p, g_E);      float* E = (float*)p;
    cudaGetSymbolAddress(&p, g_Fv);     float* Fv = (float*)p;
    cudaGetSymbolAddress(&p, g_maxtKey);unsigned* keys = (unsigned*)p;
    cudaGetSymbolAddress(&p, g_maxt);   float* maxt = (float*)p;
    cudaGetSymbolAddress(&p, g_invZ);   float* invZ = (float*)p;
    cudaGetSymbolAddress(&p, g_mask);   unsigned* mask = (unsigned*)p;
    cudaGetSymbolAddress(&p, g_part);   float* part = (float*)p;
    cudaGetSymbolAddress(&p, g_stats);  float* stats = (float*)p;

    cudaFuncSetAttribute(mma3_k<4>, cudaFuncAttributeMaxDynamicSharedMemorySize, 65536);
    cudaFuncSetAttribute(mma3_k<2>, cudaFuncAttributeMaxDynamicSharedMemorySize, 49152);

    pack_mask_k<<<NN, 128>>>(adj, mask, keys);

    // lin1 + lin2 + conv1 projection (fp32)
    gemm128_k<64, 4><<<dim3(1, 32), 256>>>(x,  lin1_w, l1, 128, 128, 64, 64, lin1_b, 0);
    gemm128_k<64, 4><<<dim3(1, 32), 256>>>(l1, lin2_w, l2, 64, 64, 64, 64, lin2_b, 0);
    gemm128_k<128, 8><<<dim3(4, 32), 256>>>(l2, conv1_W, hA, 64, 64, 512, 512, nullptr, 0);
    split_k<<<(NN * 512 + 255) / 256, 256>>>(hA, hAhi, hAlo, NN * 512);

    // weight splits (cheap)
    split_k<<<(6 * 512 * 256 + 255) / 256, 256>>>(att_W, attWhi, attWlo, 6 * 512 * 256);
    split_k<<<(1536 * 256 + 255) / 256, 256>>>(conv2_W, c2Whi, c2Wlo, 1536 * 256);

    // ---- GAT conv1 (F=512) ----
    st_k<<<dim3(NN, 1), 256>>>(hA, 0, conv1_a, 0, 512, sv, tv, keys);
    etf_k<<<dim3(8, 1), 512>>>(tv, keys, maxt, E, Fv);
    attn_k<<<NN, 256>>>(sv, E, Fv, maxt, mask, Phi, Plo, invZ);
    mma3_k<4><<<dim3(4, 32, 1), 256, 65536>>>(Phi, Plo, hAhi, hAlo,
                                              out1, out1hi, out1lo,
                                              NN, NN, 512, 512, invZ, 1, 0, 0);

    // ---- 6 head projections, batched ----
    mma3_k<4><<<dim3(2, 32, 6), 256, 65536>>>(out1hi, out1lo, attWhi, attWlo,
                                              hB6, hB6hi, hB6lo,
                                              512, 512, 256, 256, nullptr, 0,
                                              (long)512 * 256, (long)NN * 256);
    st_k<<<dim3(NN, 6), 256>>>(hB6, (long)NN * 256, att_a, 512, 256,
                               sv + NN, tv + NN, keys + 1);
    etf_k<<<dim3(8, 6), 512>>>(tv + NN, keys + 1, maxt + 1, E + NN, Fv + NN);
    for (int h = 0; h < 6; h++) {
        attn_k<<<NN, 256>>>(sv + (1 + h) * NN, E + (1 + h) * NN, Fv + (1 + h) * NN,
                            maxt + 1 + h, mask, Phi, Plo, invZ);
        mma3_k<2><<<dim3(2, 64, 1), 256, 49152>>>(Phi, Plo,
                                                  hB6hi + (size_t)h * NN * 256,
                                                  hB6lo + (size_t)h * NN * 256,
                                                  cat + (size_t)h * 256, nullptr, nullptr,
                                                  NN, NN, 256, 1536, invZ, 1, 0, 0);
    }

    // ---- GroupNorm ----
    gn_reduce1_k<<<2048, 256>>>(cat, part);
    gn_reduce2_k<<<1, 1024>>>(part, stats);
    gn_apply_k<<<(int)(((size_t)NN * 1536 + 255) / 256), 256>>>(cat, gn_w, gn_b, stats,
                                                                cathi, catlo);

    // ---- GAT conv2 (F=256) ----
    mma3_k<2><<<dim3(2, 64, 1), 256, 49152>>>(cathi, catlo, c2Whi, c2Wlo,
                                              hB, hBhi, hBlo,
                                              1536, 1536, 256, 256, nullptr, 0, 0, 0);
    st_k<<<dim3(NN, 1), 256>>>(hB, 0, conv2_a, 0, 256, sv + 7 * NN, tv + 7 * NN, keys + 7);
    etf_k<<<dim3(8, 1), 512>>>(tv + 7 * NN, keys + 7, maxt + 7, E + 7 * NN, Fv + 7 * NN);
    attn_k<<<NN, 256>>>(sv + 7 * NN, E + 7 * NN, Fv + 7 * NN, maxt + 7, mask,
                        Phi, Plo, invZ);
    mma3_k<2><<<dim3(2, 64, 1), 256, 49152>>>(Phi, Plo, hBhi, hBlo,
                                              out, nullptr, nullptr,
                                              NN, NN, 256, 256, invZ, 0, 0, 0);
}

// round 5
// speedup vs baseline: 3.1530x; 1.2308x over previous
#include <cuda_runtime.h>
#include <cuda_bf16.h>
#include <math.h>

#define NN 4096

// ---------------- scratch (device globals) ----------------
__device__ __nv_bfloat16 g_Phi[6ULL * NN * NN];   // 6 P slots (hi)
__device__ __nv_bfloat16 g_Plo[6ULL * NN * NN];   // 6 P slots (lo)
__device__ float g_hA[NN * 512];
__device__ __nv_bfloat16 g_hAhi[NN * 512];
__device__ __nv_bfloat16 g_hAlo[NN * 512];
__device__ float g_out1[NN * 512];
__device__ __nv_bfloat16 g_out1hi[NN * 512];
__device__ __nv_bfloat16 g_out1lo[NN * 512];
__device__ float g_cat[NN * 1536];
__device__ __nv_bfloat16 g_cathi[NN * 1536];
__device__ __nv_bfloat16 g_catlo[NN * 1536];
__device__ float g_hB6[6 * NN * 256];
__device__ __nv_bfloat16 g_hB6hi[6 * NN * 256];
__device__ __nv_bfloat16 g_hB6lo[6 * NN * 256];
__device__ float g_hB[NN * 256];
__device__ __nv_bfloat16 g_hBhi[NN * 256];
__device__ __nv_bfloat16 g_hBlo[NN * 256];
__device__ __nv_bfloat16 g_attWhi[6 * 512 * 256];
__device__ __nv_bfloat16 g_attWlo[6 * 512 * 256];
__device__ __nv_bfloat16 g_c2Whi[1536 * 256];
__device__ __nv_bfloat16 g_c2Wlo[1536 * 256];
__device__ float g_l1[NN * 64];
__device__ float g_l2[NN * 64];
__device__ float g_sv[8 * NN];
__device__ float g_tv[8 * NN];
__device__ float g_E[8 * NN];
__device__ float g_Fv[8 * NN];
__device__ unsigned g_maxtKey[8];
__device__ float g_maxt[8];
__device__ float g_invZ[8 * NN];
__device__ unsigned g_mask[NN * 128];
__device__ float g_part[2 * 2048];
__device__ float g_stats[2];

__device__ __forceinline__ unsigned fenc(float f) {
    unsigned u = __float_as_uint(f);
    return (u & 0x80000000u) ? ~u : (u | 0x80000000u);
}
__device__ __forceinline__ float fdec(unsigned k) {
    unsigned u = (k & 0x80000000u) ? (k & 0x7fffffffu) : ~k;
    return __uint_as_float(u);
}
__device__ __forceinline__ unsigned sptr(const void* p) {
    return (unsigned)__cvta_generic_to_shared(p);
}
__device__ __forceinline__ void cpasync16(unsigned s, const void* g) {
    asm volatile("cp.async.cg.shared.global [%0], [%1], 16;\n" :: "r"(s), "l"(g));
}
__device__ __forceinline__ void ldm_x4(unsigned a, unsigned& r0, unsigned& r1,
                                       unsigned& r2, unsigned& r3) {
    asm volatile("ldmatrix.sync.aligned.m8n8.x4.shared.b16 {%0,%1,%2,%3}, [%4];"
                 : "=r"(r0), "=r"(r1), "=r"(r2), "=r"(r3) : "r"(a));
}
__device__ __forceinline__ void ldm_x4t(unsigned a, unsigned& r0, unsigned& r1,
                                        unsigned& r2, unsigned& r3) {
    asm volatile("ldmatrix.sync.aligned.m8n8.x4.trans.shared.b16 {%0,%1,%2,%3}, [%4];"
                 : "=r"(r0), "=r"(r1), "=r"(r2), "=r"(r3) : "r"(a));
}
__device__ __forceinline__ void mma16816(float* c, const unsigned* a, const unsigned* b) {
    asm volatile(
        "mma.sync.aligned.m16n8k16.row.col.f32.bf16.bf16.f32 "
        "{%0,%1,%2,%3},{%4,%5,%6,%7},{%8,%9},{%0,%1,%2,%3};"
        : "+f"(c[0]), "+f"(c[1]), "+f"(c[2]), "+f"(c[3])
        : "r"(a[0]), "r"(a[1]), "r"(a[2]), "r"(a[3]), "r"(b[0]), "r"(b[1]));
}
__device__ __forceinline__ void split1(float v, __nv_bfloat16& hi, __nv_bfloat16& lo) {
    hi = __float2bfloat16(v);
    lo = __float2bfloat16(v - __bfloat162float(hi));
}

// ---------------- bitmask pack + maxt reset ----------------
__global__ void pack_mask_k(const int* __restrict__ adj, unsigned* __restrict__ mask,
                            unsigned* __restrict__ keys) {
    int i = blockIdx.x;
    int w = threadIdx.x;
    if (i == 0 && w < 8) keys[w] = 0u;
    const int* row = adj + (size_t)i * NN + w * 32;
    unsigned bits = 0;
#pragma unroll
    for (int b = 0; b < 32; b++) bits |= (row[b] > 0 ? 1u : 0u) << b;
    mask[i * 128 + w] = bits;
}

// ---------------- fp32 GEMM for the small projections ----------------
template <int BN, int TN>
__global__ void __launch_bounds__(256) gemm128_k(
    const float* __restrict__ A, const float* __restrict__ B, float* __restrict__ C,
    int K, int lda, int ldb, int ldc,
    const float* __restrict__ bias, int act) {
    __shared__ float As[2][16][128];
    __shared__ float Bs[2][16][BN];
    const int tid = threadIdx.x;
    const int tx = tid & 15, ty = tid >> 4;
    const int row0 = blockIdx.y * 128, col0 = blockIdx.x * BN;
    int am[2], akq[2];
#pragma unroll
    for (int i = 0; i < 2; i++) {
        int idx = tid + i * 256;
        am[i] = idx >> 2;
        akq[i] = (idx & 3) << 2;
    }
    constexpr int BCNT = (16 * BN / 4) / 256;
    int bk[BCNT], bn[BCNT];
#pragma unroll
    for (int i = 0; i < BCNT; i++) {
        int idx = tid + i * 256;
        bk[i] = idx / (BN / 4);
        bn[i] = (idx % (BN / 4)) << 2;
    }
    float acc[8][TN];
#pragma unroll
    for (int i = 0; i < 8; i++)
#pragma unroll
        for (int j = 0; j < TN; j++) acc[i][j] = 0.f;
    float4 aR[2];
    float4 bR[BCNT];
#pragma unroll
    for (int i = 0; i < 2; i++)
        aR[i] = *(const float4*)(A + (size_t)(row0 + am[i]) * lda + akq[i]);
#pragma unroll
    for (int i = 0; i < BCNT; i++)
        bR[i] = *(const float4*)(B + (size_t)bk[i] * ldb + col0 + bn[i]);
#pragma unroll
    for (int i = 0; i < 2; i++) {
        As[0][akq[i] + 0][am[i]] = aR[i].x;
        As[0][akq[i] + 1][am[i]] = aR[i].y;
        As[0][akq[i] + 2][am[i]] = aR[i].z;
        As[0][akq[i] + 3][am[i]] = aR[i].w;
    }
#pragma unroll
    for (int i = 0; i < BCNT; i++) *(float4*)&Bs[0][bk[i]][bn[i]] = bR[i];
    __syncthreads();
    const int nT = K >> 4;
    for (int t = 0; t < nT; t++) {
        const int buf = t & 1;
        if (t + 1 < nT) {
            const int k0 = (t + 1) << 4;
#pragma unroll
            for (int i = 0; i < 2; i++)
                aR[i] = *(const float4*)(A + (size_t)(row0 + am[i]) * lda + k0 + akq[i]);
#pragma unroll
            for (int i = 0; i < BCNT; i++)
                bR[i] = *(const float4*)(B + (size_t)(k0 + bk[i]) * ldb + col0 + bn[i]);
        }
#pragma unroll
        for (int kk = 0; kk < 16; kk++) {
            float4 a0 = *(const float4*)&As[buf][kk][ty * 8];
            float4 a1 = *(const float4*)&As[buf][kk][ty * 8 + 4];
            float av[8] = {a0.x, a0.y, a0.z, a0.w, a1.x, a1.y, a1.z, a1.w};
            float bv[TN];
            float4 b0 = *(const float4*)&Bs[buf][kk][tx * TN];
            bv[0] = b0.x; bv[1] = b0.y; bv[2] = b0.z; bv[3] = b0.w;
            if (TN == 8) {
                float4 b1 = *(const float4*)&Bs[buf][kk][tx * TN + 4];
                bv[4] = b1.x; bv[5] = b1.y; bv[6] = b1.z; bv[7] = b1.w;
            }
#pragma unroll
            for (int i = 0; i < 8; i++)
#pragma unroll
                for (int j = 0; j < TN; j++) acc[i][j] += av[i] * bv[j];
        }
        if (t + 1 < nT) {
            const int nb = buf ^ 1;
#pragma unroll
            for (int i = 0; i < 2; i++) {
                As[nb][akq[i] + 0][am[i]] = aR[i].x;
                As[nb][akq[i] + 1][am[i]] = aR[i].y;
                As[nb][akq[i] + 2][am[i]] = aR[i].z;
                As[nb][akq[i] + 3][am[i]] = aR[i].w;
            }
#pragma unroll
            for (int i = 0; i < BCNT; i++) *(float4*)&Bs[nb][bk[i]][bn[i]] = bR[i];
            __syncthreads();
        }
    }
#pragma unroll
    for (int i = 0; i < 8; i++) {
        int row = row0 + ty * 8 + i;
#pragma unroll
        for (int j4 = 0; j4 < TN; j4 += 4) {
            float r[4];
#pragma unroll
            for (int j = 0; j < 4; j++) {
                float x = acc[i][j4 + j];
                if (bias) x += bias[col0 + tx * TN + j4 + j];
                if (act == 1) x = fmaxf(x, 0.f);
                r[j] = x;
            }
            *(float4*)(C + (size_t)row * ldc + col0 + tx * TN + j4) =
                make_float4(r[0], r[1], r[2], r[3]);
        }
    }
}

// ---------------- 3xBF16 tensor-core GEMM, 3-stage cp.async pipeline ----------------
// C[M x N] = (Ahi+Alo) @ (Bhi+Blo), fp32 accum via hi*hi + lo*hi + hi*lo.
// BM = MT*32 (warp grid 2x4, warp tile (MT*16) x 32), BN=128, BK=32.
template <int MT>
__global__ void __launch_bounds__(256) mma3_k(
    const __nv_bfloat16* __restrict__ Ahi, const __nv_bfloat16* __restrict__ Alo,
    const __nv_bfloat16* __restrict__ Bhi, const __nv_bfloat16* __restrict__ Blo,
    float* __restrict__ C, __nv_bfloat16* __restrict__ Chi, __nv_bfloat16* __restrict__ Clo,
    int K, int lda, int ldb, int ldc,
    const float* __restrict__ rowScale, int act,
    long strideAz, long strideBz, long strideCz, int rsStride) {
    constexpr int BM = MT * 32;
    constexpr int ABYTES = BM * 128;     // BM rows x (32 hi | 32 lo) bf16 = 128B/row
    constexpr int BBYTES = 32 * 512;     // 32 k-rows x (128 hi | 128 lo) bf16 = 512B/row
    constexpr int LA = BM / 32;          // LA*256 threads cover BM*8 chunks

    extern __shared__ __align__(16) char smraw[];
    unsigned aBase = sptr(smraw);
    unsigned bBase = aBase + 3 * ABYTES;

    const int z = blockIdx.z;
    Ahi += (long)z * strideAz;
    Alo += (long)z * strideAz;
    Bhi += (long)z * strideBz;
    Blo += (long)z * strideBz;
    long cz = (long)z * strideCz;
    const int rs0 = z * rsStride;

    const int tid = threadIdx.x;
    const int w = tid >> 5, lane = tid & 31;
    const int wm = w >> 2, wn = w & 3;
    const int row0 = blockIdx.y * BM, col0 = blockIdx.x * 128;
    const int nT = K >> 5;

    auto loadTile = [&](int buf, int k0) {
#pragma unroll
        for (int i = 0; i < LA; i++) {
            int idx = i * 256 + tid;                 // 0 .. BM*8-1
            int plane = idx >= BM * 4 ? 1 : 0;
            int ii = idx - plane * BM * 4;           // 0 .. BM*4-1
            int r = ii >> 2, c4 = ii & 3;
            const __nv_bfloat16* g =
                (plane ? Alo : Ahi) + (size_t)(row0 + r) * lda + k0 + c4 * 8;
            int c = c4 + plane * 4;
            unsigned s = aBase + buf * ABYTES + r * 128 + ((c ^ (r & 7)) << 4);
            cpasync16(s, g);
        }
#pragma unroll
        for (int i = 0; i < 4; i++) {
            int idx = i * 256 + tid;
            int plane = idx >> 9;
            int ii = idx & 511;
            int k = ii >> 4, c16 = ii & 15;
            const __nv_bfloat16* g =
                (plane ? Blo : Bhi) + (size_t)(k0 + k) * ldb + col0 + c16 * 8;
            int c = c16 + plane * 16;
            int p = (c & 24) | ((c ^ k) & 7);
            unsigned s = bBase + buf * BBYTES + k * 512 + (p << 4);
            cpasync16(s, g);
        }
    };

    float acc[MT][4][4];
#pragma unroll
    for (int m = 0; m < MT; m++)
#pragma unroll
        for (int n = 0; n < 4; n++)
#pragma unroll
            for (int q = 0; q < 4; q++) acc[m][n][q] = 0.f;

    // prologue: tiles 0 and 1 (all our K >= 256, so nT >= 8)
    loadTile(0, 0);
    asm volatile("cp.async.commit_group;\n" ::);
    loadTile(1, 32);
    asm volatile("cp.async.commit_group;\n" ::);

    for (int t = 0; t < nT; t++) {
        asm volatile("cp.async.wait_group 1;\n" ::);
        __syncthreads();
        if (t + 2 < nT) {
            int bufn = (t + 2) % 3;
            loadTile(bufn, (t + 2) * 32);
        }
        asm volatile("cp.async.commit_group;\n" ::);

        const int buf = t % 3;
#pragma unroll
        for (int ks = 0; ks < 2; ks++) {
            unsigned ah[MT][4], al[MT][4], bh[4][2], bl[4][2];
#pragma unroll
            for (int mt = 0; mt < MT; mt++) {
                int rA = wm * MT * 16 + mt * 16 + (lane & 15);
                int ck = ks * 2 + (lane >> 4);
                unsigned base = aBase + buf * ABYTES + rA * 128;
                ldm_x4(base + ((ck ^ (rA & 7)) << 4),
                       ah[mt][0], ah[mt][1], ah[mt][2], ah[mt][3]);
                ldm_x4(base + (((ck + 4) ^ (rA & 7)) << 4),
                       al[mt][0], al[mt][1], al[mt][2], al[mt][3]);
            }
#pragma unroll
            for (int np = 0; np < 2; np++) {
                int kr = ks * 16 + (lane & 15);
                int cb = wn * 4 + np * 2 + (lane >> 4);
                unsigned base = bBase + buf * BBYTES + kr * 512;
                int ph = (cb & 24) | ((cb ^ kr) & 7);
                ldm_x4t(base + (ph << 4), bh[2 * np][0], bh[2 * np][1],
                        bh[2 * np + 1][0], bh[2 * np + 1][1]);
                int cl = cb + 16;
                int pl = (cl & 24) | ((cl ^ kr) & 7);
                ldm_x4t(base + (pl << 4), bl[2 * np][0], bl[2 * np][1],
                        bl[2 * np + 1][0], bl[2 * np + 1][1]);
            }
#pragma unroll
            for (int mt = 0; mt < MT; mt++)
#pragma unroll
                for (int nt = 0; nt < 4; nt++) {
                    mma16816(acc[mt][nt], ah[mt], bh[nt]);
                    mma16816(acc[mt][nt], al[mt], bh[nt]);
                    mma16816(acc[mt][nt], ah[mt], bl[nt]);
                }
        }
    }

    // epilogue
#pragma unroll
    for (int mt = 0; mt < MT; mt++) {
        int r1 = row0 + wm * MT * 16 + mt * 16 + (lane >> 2);
        int r2 = r1 + 8;
        float s1 = rowScale ? rowScale[rs0 + r1] : 1.f;
        float s2 = rowScale ? rowScale[rs0 + r2] : 1.f;
#pragma unroll
        for (int nt = 0; nt < 4; nt++) {
            int cidx = col0 + wn * 32 + nt * 8 + (lane & 3) * 2;
            float v0 = acc[mt][nt][0] * s1, v1 = acc[mt][nt][1] * s1;
            float v2 = acc[mt][nt][2] * s2, v3 = acc[mt][nt][3] * s2;
            if (act == 1) {
                v0 = fmaxf(v0, 0.f); v1 = fmaxf(v1, 0.f);
                v2 = fmaxf(v2, 0.f); v3 = fmaxf(v3, 0.f);
            }
            if (C) {
                *(float2*)(C + cz + (size_t)r1 * ldc + cidx) = make_float2(v0, v1);
                *(float2*)(C + cz + (size_t)r2 * ldc + cidx) = make_float2(v2, v3);
            }
            if (Chi) {
                __nv_bfloat162 h, l;
                split1(v0, h.x, l.x); split1(v1, h.y, l.y);
                *(__nv_bfloat162*)(Chi + cz + (size_t)r1 * ldc + cidx) = h;
                *(__nv_bfloat162*)(Clo + cz + (size_t)r1 * ldc + cidx) = l;
                split1(v2, h.x, l.x); split1(v3, h.y, l.y);
                *(__nv_bfloat162*)(Chi + cz + (size_t)r2 * ldc + cidx) = h;
                *(__nv_bfloat162*)(Clo + cz + (size_t)r2 * ldc + cidx) = l;
            }
        }
    }
}

// ---------------- split fp32 -> bf16 hi/lo planes ----------------
__global__ void split_k(const float* __restrict__ x, __nv_bfloat16* __restrict__ hi,
                        __nv_bfloat16* __restrict__ lo, int n) {
    int i = blockIdx.x * 256 + threadIdx.x;
    if (i < n) {
        __nv_bfloat16 h, l;
        split1(x[i], h, l);
        hi[i] = h; lo[i] = l;
    }
}

// ---------------- s,t ----------------
__global__ void st_k(const float* __restrict__ h, long hStride,
                     const float* __restrict__ a, long aStride, int F,
                     float* __restrict__ s, float* __restrict__ t,
                     unsigned* __restrict__ key) {
    __shared__ float r1[256], r2[256];
    int b = blockIdx.y;
    h += (long)b * hStride;
    a += (long)b * aStride;
    int i = blockIdx.x, tid = threadIdx.x;
    float as = 0.f, at = 0.f;
    for (int k = tid; k < F; k += 256) {
        float v = h[(size_t)i * F + k];
        as += v * a[k];
        at += v * a[F + k];
    }
    r1[tid] = as; r2[tid] = at;
    __syncthreads();
    for (int s2 = 128; s2 > 0; s2 >>= 1) {
        if (tid < s2) { r1[tid] += r1[tid + s2]; r2[tid] += r2[tid + s2]; }
        __syncthreads();
    }
    if (tid == 0) {
        s[b * NN + i] = r1[0];
        t[b * NN + i] = r2[0];
        atomicMax(&key[b], fenc(r2[0]));
    }
}

__global__ void etf_k(const float* __restrict__ t, const unsigned* __restrict__ key,
                      float* __restrict__ maxt, float* __restrict__ E,
                      float* __restrict__ Fv) {
    int b = blockIdx.y;
    float mt = fdec(key[b]);
    if (blockIdx.x == 0 && threadIdx.x == 0) maxt[b] = mt;
    int j = blockIdx.x * 512 + threadIdx.x;
    float tv = t[b * NN + j] - mt;
    E[b * NN + j] = expf(tv);
    Fv[b * NN + j] = expf(0.2f * tv);
}

// ---------------- per-row masked softmax weights -> bf16 hi/lo planes ----------------
// p = mask ? max(c*E_j, d*F_j) : 0   (exp monotone over the two lrelu branches)
// z-batched: blockIdx.y selects slot (s, E, F, maxt, P planes, invZ).
__global__ void attn_k(const float* __restrict__ s, const float* __restrict__ E,
                       const float* __restrict__ Fv, const float* __restrict__ maxt,
                       const unsigned* __restrict__ mask,
                       __nv_bfloat16* __restrict__ Phi, __nv_bfloat16* __restrict__ Plo,
                       float* __restrict__ invZ) {
    __shared__ float shE[NN];
    __shared__ float shF[NN];
    __shared__ unsigned shm[128];
    __shared__ float red[256];
    const int z = blockIdx.y;
    s += (size_t)z * NN;
    E += (size_t)z * NN;
    Fv += (size_t)z * NN;
    Phi += (size_t)z * NN * NN;
    Plo += (size_t)z * NN * NN;
    invZ += (size_t)z * NN;

    int i = blockIdx.x, tid = threadIdx.x;
#pragma unroll
    for (int j = 0; j < 4; j++) {
        ((float4*)shE)[j * 256 + tid] = ((const float4*)E)[j * 256 + tid];
        ((float4*)shF)[j * 256 + tid] = ((const float4*)Fv)[j * 256 + tid];
    }
    if (tid < 128) shm[tid] = mask[i * 128 + tid];
    __syncthreads();

    float q = s[i] + maxt[z];
    float m = fmaxf(q, 0.2f * q);
    float c = expf(q - m);
    float d = expf(0.2f * q - m);

    float sum = 0.f;
    __nv_bfloat16* PhiRow = Phi + (size_t)i * NN;
    __nv_bfloat16* PloRow = Plo + (size_t)i * NN;
#pragma unroll
    for (int it = 0; it < 2; it++) {
        int chunk = it * 256 + tid;          // 0..511, 8 elems each
        int j0 = chunk * 8;
        unsigned mbyte = (shm[j0 >> 5] >> (j0 & 31)) & 0xFFu;
        float4 e0 = ((const float4*)shE)[chunk * 2];
        float4 e1 = ((const float4*)shE)[chunk * 2 + 1];
        float4 f0 = ((const float4*)shF)[chunk * 2];
        float4 f1 = ((const float4*)shF)[chunk * 2 + 1];
        float e[8] = {e0.x, e0.y, e0.z, e0.w, e1.x, e1.y, e1.z, e1.w};
        float f[8] = {f0.x, f0.y, f0.z, f0.w, f1.x, f1.y, f1.z, f1.w};
        __nv_bfloat16 hb[8], lb[8];
#pragma unroll
        for (int k = 0; k < 8; k++) {
            float p = ((mbyte >> k) & 1u) ? fmaxf(c * e[k], d * f[k]) : 0.f;
            sum += p;
            split1(p, hb[k], lb[k]);
        }
        *(uint4*)(PhiRow + j0) = *(const uint4*)hb;
        *(uint4*)(PloRow + j0) = *(const uint4*)lb;
    }
    red[tid] = sum;
    __syncthreads();
    for (int s2 = 128; s2 > 0; s2 >>= 1) {
        if (tid < s2) red[tid] += red[tid + s2];
        __syncthreads();
    }
    if (tid == 0) invZ[i] = 1.f / red[0];
}

// ---------------- GroupNorm ----------------
__global__ void gn_reduce1_k(const float* __restrict__ h, float* __restrict__ part) {
    __shared__ float r1[256], r2[256];
    int tid = threadIdx.x;
    float s = 0.f, q = 0.f;
    for (size_t idx = (size_t)blockIdx.x * 256 + tid; idx < (size_t)NN * 1536;
         idx += (size_t)2048 * 256) {
        float v = h[idx];
        s += v;
        q += v * v;
    }
    r1[tid] = s; r2[tid] = q;
    __syncthreads();
    for (int s2 = 128; s2 > 0; s2 >>= 1) {
        if (tid < s2) { r1[tid] += r1[tid + s2]; r2[tid] += r2[tid + s2]; }
        __syncthreads();
    }
    if (tid == 0) { part[blockIdx.x] = r1[0]; part[2048 + blockIdx.x] = r2[0]; }
}

__global__ void gn_reduce2_k(const float* __restrict__ part, float* __restrict__ stats) {
    __shared__ double r1[1024], r2[1024];
    int tid = threadIdx.x;
    double s = 0.0, q = 0.0;
    for (int i = tid; i < 2048; i += 1024) { s += part[i]; q += part[2048 + i]; }
    r1[tid] = s; r2[tid] = q;
    __syncthreads();
    for (int s2 = 512; s2 > 0; s2 >>= 1) {
        if (tid < s2) { r1[tid] += r1[tid + s2]; r2[tid] += r2[tid + s2]; }
        __syncthreads();
    }
    if (tid == 0) {
        double n = (double)NN * 1536.0;
        double mu = r1[0] / n;
        double var = (r2[0] - n * mu * mu) / (n - 1.0);
        stats[0] = (float)mu;
        stats[1] = (float)(1.0 / sqrt(var + 1e-5));
    }
}

__global__ void gn_apply_k(const float* __restrict__ h, const float* __restrict__ w,
                           const float* __restrict__ b, const float* __restrict__ stats,
                           __nv_bfloat16* __restrict__ hi, __nv_bfloat16* __restrict__ lo) {
    size_t idx = (size_t)blockIdx.x * 256 + threadIdx.x;
    if (idx < (size_t)NN * 1536) {
        int c = (int)(idx % 1536);
        float v = (h[idx] - stats[0]) * stats[1] * w[c] + b[c];
        __nv_bfloat16 hh, ll;
        split1(v, hh, ll);
        hi[idx] = hh; lo[idx] = ll;
    }
}

// ---------------- host ----------------
extern "C" void kernel_launch(void* const* d_in, const int* in_sizes, int n_in,
                              void* d_out, int out_size) {
    const float* x       = (const float*)d_in[0];
    const int*   adj     = (const int*)d_in[1];
    const float* lin1_w  = (const float*)d_in[2];
    const float* lin1_b  = (const float*)d_in[3];
    const float* lin2_w  = (const float*)d_in[4];
    const float* lin2_b  = (const float*)d_in[5];
    const float* conv1_W = (const float*)d_in[6];
    const float* conv1_a = (const float*)d_in[7];
    const float* att_W   = (const float*)d_in[8];
    const float* att_a   = (const float*)d_in[9];
    const float* gn_w    = (const float*)d_in[10];
    const float* gn_b    = (const float*)d_in[11];
    const float* conv2_W = (const float*)d_in[12];
    const float* conv2_a = (const float*)d_in[13];
    float* out = (float*)d_out;

    void* p;
    cudaGetSymbolAddress(&p, g_Phi);    __nv_bfloat16* Phi = (__nv_bfloat16*)p;
    cudaGetSymbolAddress(&p, g_Plo);    __nv_bfloat16* Plo = (__nv_bfloat16*)p;
    cudaGetSymbolAddress(&p, g_hA);     float* hA = (float*)p;
    cudaGetSymbolAddress(&p, g_hAhi);   __nv_bfloat16* hAhi = (__nv_bfloat16*)p;
    cudaGetSymbolAddress(&p, g_hAlo);   __nv_bfloat16* hAlo = (__nv_bfloat16*)p;
    cudaGetSymbolAddress(&p, g_out1);   float* out1 = (float*)p;
    cudaGetSymbolAddress(&p, g_out1hi); __nv_bfloat16* out1hi = (__nv_bfloat16*)p;
    cudaGetSymbolAddress(&p, g_out1lo); __nv_bfloat16* out1lo = (__nv_bfloat16*)p;
    cudaGetSymbolAddress(&p, g_cat);    float* cat = (float*)p;
    cudaGetSymbolAddress(&p, g_cathi);  __nv_bfloat16* cathi = (__nv_bfloat16*)p;
    cudaGetSymbolAddress(&p, g_catlo);  __nv_bfloat16* catlo = (__nv_bfloat16*)p;
    cudaGetSymbolAddress(&p, g_hB6);    float* hB6 = (float*)p;
    cudaGetSymbolAddress(&p, g_hB6hi);  __nv_bfloat16* hB6hi = (__nv_bfloat16*)p;
    cudaGetSymbolAddress(&p, g_hB6lo);  __nv_bfloat16* hB6lo = (__nv_bfloat16*)p;
    cudaGetSymbolAddress(&p, g_hB);     float* hB = (float*)p;
    cudaGetSymbolAddress(&p, g_hBhi);   __nv_bfloat16* hBhi = (__nv_bfloat16*)p;
    cudaGetSymbolAddress(&p, g_hBlo);   __nv_bfloat16* hBlo = (__nv_bfloat16*)p;
    cudaGetSymbolAddress(&p, g_attWhi); __nv_bfloat16* attWhi = (__nv_bfloat16*)p;
    cudaGetSymbolAddress(&p, g_attWlo); __nv_bfloat16* attWlo = (__nv_bfloat16*)p;
    cudaGetSymbolAddress(&p, g_c2Whi);  __nv_bfloat16* c2Whi = (__nv_bfloat16*)p;
    cudaGetSymbolAddress(&p, g_c2Wlo);  __nv_bfloat16* c2Wlo = (__nv_bfloat16*)p;
    cudaGetSymbolAddress(&p, g_l1);     float* l1 = (float*)p;
    cudaGetSymbolAddress(&p, g_l2);     float* l2 = (float*)p;
    cudaGetSymbolAddress(&p, g_sv);     float* sv = (float*)p;
    cudaGetSymbolAddress(&p, g_tv);     float* tv = (float*)p;
    cudaGetSymbolAddress(&p, g_E);      float* E = (float*)p;
    cudaGetSymbolAddress(&p, g_Fv);     float* Fv = (float*)p;
    cudaGetSymbolAddress(&p, g_maxtKey);unsigned* keys = (unsigned*)p;
    cudaGetSymbolAddress(&p, g_maxt);   float* maxt = (float*)p;
    cudaGetSymbolAddress(&p, g_invZ);   float* invZ = (float*)p;
    cudaGetSymbolAddress(&p, g_mask);   unsigned* mask = (unsigned*)p;
    cudaGetSymbolAddress(&p, g_part);   float* part = (float*)p;
    cudaGetSymbolAddress(&p, g_stats);  float* stats = (float*)p;

    cudaFuncSetAttribute(mma3_k<4>, cudaFuncAttributeMaxDynamicSharedMemorySize, 98304);
    cudaFuncSetAttribute(mma3_k<2>, cudaFuncAttributeMaxDynamicSharedMemorySize, 73728);

    pack_mask_k<<<NN, 128>>>(adj, mask, keys);

    // lin1 + lin2 + conv1 projection (fp32)
    gemm128_k<64, 4><<<dim3(1, 32), 256>>>(x,  lin1_w, l1, 128, 128, 64, 64, lin1_b, 0);
    gemm128_k<64, 4><<<dim3(1, 32), 256>>>(l1, lin2_w, l2, 64, 64, 64, 64, lin2_b, 0);
    gemm128_k<128, 8><<<dim3(4, 32), 256>>>(l2, conv1_W, hA, 64, 64, 512, 512, nullptr, 0);
    split_k<<<(NN * 512 + 255) / 256, 256>>>(hA, hAhi, hAlo, NN * 512);

    // weight splits (cheap)
    split_k<<<(6 * 512 * 256 + 255) / 256, 256>>>(att_W, attWhi, attWlo, 6 * 512 * 256);
    split_k<<<(1536 * 256 + 255) / 256, 256>>>(conv2_W, c2Whi, c2Wlo, 1536 * 256);

    // ---- GAT conv1 (F=512): P slot 0, invZ slot 0 ----
    st_k<<<dim3(NN, 1), 256>>>(hA, 0, conv1_a, 0, 512, sv, tv, keys);
    etf_k<<<dim3(8, 1), 512>>>(tv, keys, maxt, E, Fv);
    attn_k<<<dim3(NN, 1), 256>>>(sv, E, Fv, maxt, mask, Phi, Plo, invZ);
    mma3_k<4><<<dim3(4, 32, 1), 256, 98304>>>(Phi, Plo, hAhi, hAlo,
                                              out1, out1hi, out1lo,
                                              NN, NN, 512, 512, invZ, 1,
                                              0, 0, 0, 0);

    // ---- 6 head projections, batched ----
    mma3_k<4><<<dim3(2, 32, 6), 256, 98304>>>(out1hi, out1lo, attWhi, attWlo,
                                              hB6, hB6hi, hB6lo,
                                              512, 512, 256, 256, nullptr, 0,
                                              0, (long)512 * 256, (long)NN * 256, 0);
    st_k<<<dim3(NN, 6), 256>>>(hB6, (long)NN * 256, att_a, 512, 256,
                               sv + NN, tv + NN, keys + 1);
    etf_k<<<dim3(8, 6), 512>>>(tv + NN, keys + 1, maxt + 1, E + NN, Fv + NN);
    // all 6 head attentions -> P slots 0..5, invZ slots 0..5
    attn_k<<<dim3(NN, 6), 256>>>(sv + NN, E + NN, Fv + NN, maxt + 1, mask,
                                 Phi, Plo, invZ);
    // all 6 head P@h GEMMs in one launch
    mma3_k<4><<<dim3(2, 32, 6), 256, 98304>>>(Phi, Plo, hB6hi, hB6lo,
                                              cat, nullptr, nullptr,
                                              NN, NN, 256, 1536, invZ, 1,
                                              (long)NN * NN, (long)NN * 256, 256, NN);

    // ---- GroupNorm ----
    gn_reduce1_k<<<2048, 256>>>(cat, part);
    gn_reduce2_k<<<1, 1024>>>(part, stats);
    gn_apply_k<<<(int)(((size_t)NN * 1536 + 255) / 256), 256>>>(cat, gn_w, gn_b, stats,
                                                                cathi, catlo);

    // ---- GAT conv2 (F=256): P slot 0, invZ slot 0, data slot 7 ----
    mma3_k<2><<<dim3(2, 64, 1), 256, 73728>>>(cathi, catlo, c2Whi, c2Wlo,
                                              hB, hBhi, hBlo,
                                              1536, 1536, 256, 256, nullptr, 0,
                                              0, 0, 0, 0);
    st_k<<<dim3(NN, 1), 256>>>(hB, 0, conv2_a, 0, 256, sv + 7 * NN, tv + 7 * NN, keys + 7);
    etf_k<<<dim3(8, 1), 512>>>(tv + 7 * NN, keys + 7, maxt + 7, E + 7 * NN, Fv + 7 * NN);
    attn_k<<<dim3(NN, 1), 256>>>(sv + 7 * NN, E + 7 * NN, Fv + 7 * NN, maxt + 7, mask,
                                 Phi, Plo, invZ);
    mma3_k<2><<<dim3(2, 64, 1), 256, 73728>>>(Phi, Plo, hBhi, hBlo,
                                              out, nullptr, nullptr,
                                              NN, NN, 256, 256, invZ, 0,
                                              0, 0, 0, 0);
}